// round 12
// baseline (speedup 1.0000x reference)
#include <cuda_runtime.h>
#include <cuda_bf16.h>
#include <cstdint>

// ===================== problem dims / tiles =====================
static constexpr int T     = 4096;   // tokens (M)
static constexpr int IN_F  = 4096;   // K
static constexpr int OUT_F = 4096;   // N
static constexpr int KC    = 64;     // K chunk bytes (int8)
static constexpr int KITERS = IN_F / KC;   // 64
static constexpr int ROWB  = 80;     // smem row stride (conflict-free ldmatrix + lds)
static constexpr int STAGES = 4;
static constexpr int SSTR  = 256 * ROWB;             // bytes per stage (A rows 0-127, B rows 128-255)
static constexpr int SMEM_TOTAL = STAGES * SSTR;     // 81920
// N-split: tensor cols [0,72), dp4a cols [72,128)   (R10-verified optimum)
static constexpr int NB_MMA = 9;     // 9 x 8 = 72 tensor cols
static constexpr int DPC0   = 72;    // dp4a col base
static constexpr int DPJ    = 7;     // dp4a col-blocks (7 x 8 = 56 cols)

// ===================== device scratch =====================
__device__ float g_partial[2048];
__device__ float g_scale;
__device__ float g_inv;
__device__ __align__(16) int8_t g_qx[(size_t)T * IN_F];     // 16MB quantized activations
__device__ __align__(16) int8_t g_wt[(size_t)OUT_F * IN_F]; // 16MB int8 weights

// ===================== helpers =====================
__device__ __forceinline__ uint32_t smem_u32(const void* p) {
    uint32_t a;
    asm("{ .reg .u64 t; cvta.to.shared.u64 t, %1; cvt.u32.u64 %0, t; }" : "=r"(a) : "l"(p));
    return a;
}
__device__ __forceinline__ void ldsm_x4(uint32_t* r, uint32_t addr) {
    asm volatile("ldmatrix.sync.aligned.m8n8.x4.shared.b16 {%0,%1,%2,%3}, [%4];"
                 : "=r"(r[0]), "=r"(r[1]), "=r"(r[2]), "=r"(r[3]) : "r"(addr));
}
__device__ __forceinline__ void mma_s8(int* c, const uint32_t* a, const uint32_t* b) {
    asm volatile(
        "mma.sync.aligned.m16n8k32.row.col.s32.s8.s8.s32 "
        "{%0,%1,%2,%3}, {%4,%5,%6,%7}, {%8,%9}, {%0,%1,%2,%3};"
        : "+r"(c[0]), "+r"(c[1]), "+r"(c[2]), "+r"(c[3])
        : "r"(a[0]), "r"(a[1]), "r"(a[2]), "r"(a[3]), "r"(b[0]), "r"(b[1]));
}
__device__ __forceinline__ void lds64(int& v0, int& v1, uint32_t addr) {
    asm volatile("ld.shared.v2.b32 {%0,%1}, [%2];" : "=r"(v0), "=r"(v1) : "r"(addr));
}
__device__ __forceinline__ void cp16(uint32_t saddr, const void* gaddr) {
    asm volatile("cp.async.cg.shared.global [%0], [%1], 16;" :: "r"(saddr), "l"(gaddr));
}
__device__ __forceinline__ void cp_commit() {
    asm volatile("cp.async.commit_group;" ::: "memory");
}
__device__ __forceinline__ void cp_wait0() {
    asm volatile("cp.async.wait_group 0;" ::: "memory");
}

// ===================== stage 1: max|x| =====================
__global__ void k_maxabs(const float* __restrict__ x) {
    __shared__ float red[256];
    float m = 0.f;
    const float4* x4 = (const float4*)x;
    const int n4 = T * IN_F / 4;
    for (int i = blockIdx.x * blockDim.x + threadIdx.x; i < n4; i += gridDim.x * blockDim.x) {
        float4 v = x4[i];
        m = fmaxf(m, fmaxf(fmaxf(fabsf(v.x), fabsf(v.y)), fmaxf(fabsf(v.z), fabsf(v.w))));
    }
    red[threadIdx.x] = m;
    __syncthreads();
    #pragma unroll
    for (int s = 128; s > 0; s >>= 1) {
        if (threadIdx.x < s) red[threadIdx.x] = fmaxf(red[threadIdx.x], red[threadIdx.x + s]);
        __syncthreads();
    }
    if (threadIdx.x == 0) g_partial[blockIdx.x] = red[0];
}

__global__ void k_finalize() {
    __shared__ float red[1024];
    red[threadIdx.x] = fmaxf(g_partial[threadIdx.x], g_partial[threadIdx.x + 1024]);
    __syncthreads();
    #pragma unroll
    for (int s = 512; s > 0; s >>= 1) {
        if (threadIdx.x < s) red[threadIdx.x] = fmaxf(red[threadIdx.x], red[threadIdx.x + s]);
        __syncthreads();
    }
    if (threadIdx.x == 0) {
        float sc = __fdiv_rn(red[0], 127.0f);
        g_scale = sc;
        g_inv = __fdiv_rn(1.0f, sc);
    }
}

// ===================== stage 2: fused quantize-x + weight-convert =====================
__global__ void k_prep(const float* __restrict__ x, const int* __restrict__ w) {
    const int HALF = 1024;
    const int n4 = T * IN_F / 4;
    if (blockIdx.x < HALF) {
        const float inv = g_inv;
        const float4* x4 = (const float4*)x;
        uint32_t* o = (uint32_t*)g_qx;
        for (int i = blockIdx.x * blockDim.x + threadIdx.x; i < n4; i += HALF * blockDim.x) {
            float4 v = x4[i];
            int q0 = __float2int_rn(v.x * inv);
            int q1 = __float2int_rn(v.y * inv);
            int q2 = __float2int_rn(v.z * inv);
            int q3 = __float2int_rn(v.w * inv);
            o[i] = (q0 & 0xFF) | ((q1 & 0xFF) << 8) | ((q2 & 0xFF) << 16) | ((uint32_t)(q3 & 0xFF) << 24);
        }
    } else {
        const int4* w4 = (const int4*)w;
        uint32_t* o = (uint32_t*)g_wt;
        for (int i = (blockIdx.x - HALF) * blockDim.x + threadIdx.x; i < n4; i += HALF * blockDim.x) {
            int4 v = w4[i];
            o[i] = (v.x & 0xFF) | ((v.y & 0xFF) << 8) | ((v.z & 0xFF) << 16) | ((uint32_t)(v.w & 0xFF) << 24);
        }
    }
}

// ===================== stage 3: per-warp fused tensor+dp4a GEMM, 2-chunk barrier period =====================
// CTA 128x128, 8 warps (one per 16 M-rows), 2 CTAs/SM, split 72/56.
// 32 barrier periods; each consumes 2 K-chunks and prefetches the next 2.
__global__ void __launch_bounds__(256, 2) k_gemm(const float* __restrict__ wscale,
                                                 const float* __restrict__ bias,
                                                 float* __restrict__ out) {
    extern __shared__ __align__(16) char smem[];
    const uint32_t sbase = smem_u32(smem);

    const int tid  = threadIdx.x;
    const int lane = tid & 31;
    const int wid  = tid >> 5;
    const int Mbase = blockIdx.y * 128;
    const int Nbase = blockIdx.x * 128;

    // ---- staging (all 256 threads): A rows r0, r0+64; B rows 128+r0, 192+r0 ----
    const int r0 = tid >> 2;             // 0..63
    const int cb = (tid & 3) * 16;       // byte col in 64B chunk
    const int8_t* gA0 = g_qx + (size_t)(Mbase + r0)      * IN_F + cb;
    const int8_t* gA1 = g_qx + (size_t)(Mbase + r0 + 64) * IN_F + cb;
    const int8_t* gB0 = g_wt + (size_t)(Nbase + r0)      * IN_F + cb;
    const int8_t* gB1 = g_wt + (size_t)(Nbase + r0 + 64) * IN_F + cb;
    const uint32_t sA0 = sbase + (uint32_t)r0 * ROWB + cb;
    const uint32_t sA1 = sA0 + 64u * ROWB;
    const uint32_t sB0 = sA0 + 128u * ROWB;
    const uint32_t sB1 = sA0 + 192u * ROWB;

    // ---- mma mapping: warp wid owns rows [16*wid, 16*wid+16), cols [0,72) ----
    const int tile = lane >> 3;
    const int sub  = lane & 7;
    const uint32_t aoffw = sbase + (uint32_t)(wid * 16 + (tile & 1) * 8 + sub) * ROWB
                         + (uint32_t)(tile >> 1) * 16;
    uint32_t boff[5];
    #pragma unroll
    for (int p = 0; p < 5; ++p)       // 5 x4-LDSMs cover fragment cols [0,80); MMAs use first 9 blocks
        boff[p] = sbase + (uint32_t)(128 + p * 16 + (tile >> 1) * 8 + sub) * ROWB
                + (uint32_t)(tile & 1) * 16;

    // ---- dp4a mapping: warp wid rows [16*wid,16*wid+16), cols [72,128) ----
    const int trow = lane >> 3;          // 0..3 -> rows 16*wid + trow + 4i
    const int tcol = lane & 7;           // 0..7 -> cols 72 + tcol + 8j (j<7)
    const uint32_t dA = sbase + (uint32_t)(wid * 16 + trow) * ROWB;       // +i*4*ROWB
    const uint32_t dB = sbase + (uint32_t)(128 + DPC0 + tcol) * ROWB;     // +j*8*ROWB

    int acc[NB_MMA][4];                  // mma accumulators (16x72)
    #pragma unroll
    for (int nb = 0; nb < NB_MMA; ++nb)
        #pragma unroll
        for (int f = 0; f < 4; ++f) acc[nb][f] = 0;
    int dacc[4][DPJ];                    // dp4a accumulators (16x56 warp tile)
    #pragma unroll
    for (int i = 0; i < 4; ++i)
        #pragma unroll
        for (int j = 0; j < DPJ; ++j) dacc[i][j] = 0;

    // prologue: issue stages 0,1
    #pragma unroll
    for (int s = 0; s < 2; ++s) {
        const uint32_t so = (uint32_t)s * SSTR;
        const int ko = s * KC;
        cp16(sA0 + so, gA0 + ko);
        cp16(sA1 + so, gA1 + ko);
        cp16(sB0 + so, gB0 + ko);
        cp16(sB1 + so, gB1 + ko);
        cp_commit();
    }

    for (int p = 0; p < KITERS / 2; ++p) {
        const int it0 = 2 * p;
        cp_wait0();                 // stages it0, it0+1 landed
        __syncthreads();            // all warps done reading the slots we're about to overwrite

        // prefetch next period's stages (slots freed before this barrier)
        #pragma unroll
        for (int h = 2; h < 4; ++h) {
            const int itn = it0 + h;
            if (itn < KITERS) {
                const uint32_t so = (uint32_t)(itn & (STAGES - 1)) * SSTR;
                const int ko = itn * KC;
                cp16(sA0 + so, gA0 + ko);
                cp16(sA1 + so, gA1 + ko);
                cp16(sB0 + so, gB0 + ko);
                cp16(sB1 + so, gB1 + ko);
                cp_commit();
            }
        }

        // consume stages it0, it0+1 back-to-back (no barrier between)
        #pragma unroll
        for (int h = 0; h < 2; ++h) {
            const uint32_t so = (uint32_t)((it0 + h) & (STAGES - 1)) * SSTR;

            // ---------- tensor path: fragments loaded per-p, consumed immediately ----------
            #pragma unroll
            for (int ks = 0; ks < 2; ++ks) {
                uint32_t af[4];
                ldsm_x4(af, aoffw + so + ks * 32);
                #pragma unroll
                for (int q = 0; q < 5; ++q) {
                    uint32_t r[4];
                    ldsm_x4(r, boff[q] + so + ks * 32);
                    mma_s8(acc[q * 2], af, r);                 // n-block 2q (always < 9)
                    if (q * 2 + 1 < NB_MMA)
                        mma_s8(acc[q * 2 + 1], af, r + 2);     // n-block 2q+1 (skip 10th)
                }
            }

            // ---------- dp4a path: streams on fma/alu pipe while IMMAs drain ----------
            #pragma unroll
            for (int qb = 0; qb < 8; ++qb) {   // 8 q-pairs = 16 x 4-byte K-words
                int a0[4], a1[4], b0[DPJ], b1[DPJ];
                #pragma unroll
                for (int i = 0; i < 4; ++i)
                    lds64(a0[i], a1[i], dA + so + (uint32_t)i * (4u * ROWB) + (uint32_t)qb * 8u);
                #pragma unroll
                for (int j = 0; j < DPJ; ++j)
                    lds64(b0[j], b1[j], dB + so + (uint32_t)j * (8u * ROWB) + (uint32_t)qb * 8u);
                #pragma unroll
                for (int i = 0; i < 4; ++i)
                    #pragma unroll
                    for (int j = 0; j < DPJ; ++j) {
                        dacc[i][j] = __dp4a(a0[i], b0[j], dacc[i][j]);
                        dacc[i][j] = __dp4a(a1[i], b1[j], dacc[i][j]);
                    }
            }
        }
    }

    // ---------- epilogue: exact int32 -> fp32 scale + bias ----------
    const float s = g_scale * wscale[0];
    {   // mma tile: cols [0,72)
        const int g   = lane >> 2;
        const int tg2 = (lane & 3) * 2;
        const int row = Mbase + wid * 16 + g;
        #pragma unroll
        for (int nb = 0; nb < NB_MMA; ++nb) {
            const int col = Nbase + nb * 8 + tg2;
            const float2 bb = *(const float2*)(bias + col);
            float2 v0, v1;
            v0.x = fmaf((float)acc[nb][0], s, bb.x);
            v0.y = fmaf((float)acc[nb][1], s, bb.y);
            v1.x = fmaf((float)acc[nb][2], s, bb.x);
            v1.y = fmaf((float)acc[nb][3], s, bb.y);
            *(float2*)(out + (size_t)row * OUT_F + col)       = v0;
            *(float2*)(out + (size_t)(row + 8) * OUT_F + col) = v1;
        }
    }
    {   // dp4a tile: cols [72,128)
        #pragma unroll
        for (int j = 0; j < DPJ; ++j) {
            const int col = Nbase + DPC0 + tcol + 8 * j;
            const float bj = bias[col];
            #pragma unroll
            for (int i = 0; i < 4; ++i) {
                const int row = Mbase + wid * 16 + trow + 4 * i;
                out[(size_t)row * OUT_F + col] = fmaf((float)dacc[i][j], s, bj);
            }
        }
    }
}

// ===================== launch =====================
extern "C" void kernel_launch(void* const* d_in, const int* in_sizes, int n_in,
                              void* d_out, int out_size) {
    const float* x    = (const float*)d_in[0];
    const int*   qw   = (const int*)d_in[1];
    const float* ws   = (const float*)d_in[2];
    const float* bias = (const float*)d_in[3];
    float* out = (float*)d_out;

    k_maxabs<<<2048, 256>>>(x);
    k_finalize<<<1, 1024>>>();
    k_prep<<<2048, 256>>>(x, qw);
    cudaFuncSetAttribute(k_gemm, cudaFuncAttributeMaxDynamicSharedMemorySize, SMEM_TOTAL);
    k_gemm<<<dim3(OUT_F / 128, T / 128), 256, SMEM_TOTAL>>>(ws, bias, out);
}

// round 13
// speedup vs baseline: 1.0108x; 1.0108x over previous
#include <cuda_runtime.h>
#include <cuda_bf16.h>
#include <cstdint>

// ===================== problem dims / tiles =====================
static constexpr int T     = 4096;   // tokens (M)
static constexpr int IN_F  = 4096;   // K
static constexpr int OUT_F = 4096;   // N
static constexpr int KC    = 64;     // K chunk bytes (int8)
static constexpr int KITERS = IN_F / KC;   // 64
static constexpr int ROWB  = 80;     // smem row stride (conflict-free ldmatrix + lds)
static constexpr int STAGES = 4;
static constexpr int SSTR  = 256 * ROWB;             // bytes per stage (A rows 0-127, B rows 128-255)
static constexpr int SMEM_TOTAL = STAGES * SSTR;     // 81920
// N-split: tensor cols [0,72), dp4a cols [72,128)   (R10-verified optimum)
static constexpr int NB_MMA = 9;     // 9 x 8 = 72 tensor cols
static constexpr int DPC0   = 72;    // dp4a col base
static constexpr int DPJ    = 7;     // dp4a col-blocks (7 x 8 = 56 cols)

// ===================== device scratch =====================
__device__ float g_partial[2048];
__device__ float g_scale;
__device__ float g_inv;
__device__ __align__(16) int8_t g_qx[(size_t)T * IN_F];     // 16MB quantized activations
__device__ __align__(16) int8_t g_wt[(size_t)OUT_F * IN_F]; // 16MB int8 weights

// ===================== helpers =====================
__device__ __forceinline__ uint32_t smem_u32(const void* p) {
    uint32_t a;
    asm("{ .reg .u64 t; cvta.to.shared.u64 t, %1; cvt.u32.u64 %0, t; }" : "=r"(a) : "l"(p));
    return a;
}
__device__ __forceinline__ void ldsm_x4(uint32_t* r, uint32_t addr) {
    asm volatile("ldmatrix.sync.aligned.m8n8.x4.shared.b16 {%0,%1,%2,%3}, [%4];"
                 : "=r"(r[0]), "=r"(r[1]), "=r"(r[2]), "=r"(r[3]) : "r"(addr));
}
__device__ __forceinline__ void mma_s8(int* c, const uint32_t* a, const uint32_t* b) {
    asm volatile(
        "mma.sync.aligned.m16n8k32.row.col.s32.s8.s8.s32 "
        "{%0,%1,%2,%3}, {%4,%5,%6,%7}, {%8,%9}, {%0,%1,%2,%3};"
        : "+r"(c[0]), "+r"(c[1]), "+r"(c[2]), "+r"(c[3])
        : "r"(a[0]), "r"(a[1]), "r"(a[2]), "r"(a[3]), "r"(b[0]), "r"(b[1]));
}
__device__ __forceinline__ void lds64(int& v0, int& v1, uint32_t addr) {
    asm volatile("ld.shared.v2.b32 {%0,%1}, [%2];" : "=r"(v0), "=r"(v1) : "r"(addr));
}
__device__ __forceinline__ void cp16(uint32_t saddr, const void* gaddr) {
    asm volatile("cp.async.cg.shared.global [%0], [%1], 16;" :: "r"(saddr), "l"(gaddr));
}
__device__ __forceinline__ void cp_commit() {
    asm volatile("cp.async.commit_group;" ::: "memory");
}
__device__ __forceinline__ void cp_wait2() {
    asm volatile("cp.async.wait_group 2;" ::: "memory");
}

// ===================== stage 1: max|x| =====================
__global__ void k_maxabs(const float* __restrict__ x) {
    __shared__ float red[256];
    float m = 0.f;
    const float4* x4 = (const float4*)x;
    const int n4 = T * IN_F / 4;
    for (int i = blockIdx.x * blockDim.x + threadIdx.x; i < n4; i += gridDim.x * blockDim.x) {
        float4 v = x4[i];
        m = fmaxf(m, fmaxf(fmaxf(fabsf(v.x), fabsf(v.y)), fmaxf(fabsf(v.z), fabsf(v.w))));
    }
    red[threadIdx.x] = m;
    __syncthreads();
    #pragma unroll
    for (int s = 128; s > 0; s >>= 1) {
        if (threadIdx.x < s) red[threadIdx.x] = fmaxf(red[threadIdx.x], red[threadIdx.x + s]);
        __syncthreads();
    }
    if (threadIdx.x == 0) g_partial[blockIdx.x] = red[0];
}

__global__ void k_finalize() {
    __shared__ float red[1024];
    red[threadIdx.x] = fmaxf(g_partial[threadIdx.x], g_partial[threadIdx.x + 1024]);
    __syncthreads();
    #pragma unroll
    for (int s = 512; s > 0; s >>= 1) {
        if (threadIdx.x < s) red[threadIdx.x] = fmaxf(red[threadIdx.x], red[threadIdx.x + s]);
        __syncthreads();
    }
    if (threadIdx.x == 0) {
        float sc = __fdiv_rn(red[0], 127.0f);
        g_scale = sc;
        g_inv = __fdiv_rn(1.0f, sc);
    }
}

// ===================== stage 2: fused quantize-x + weight-convert =====================
__global__ void k_prep(const float* __restrict__ x, const int* __restrict__ w) {
    const int HALF = 1024;
    const int n4 = T * IN_F / 4;
    if (blockIdx.x < HALF) {
        const float inv = g_inv;
        const float4* x4 = (const float4*)x;
        uint32_t* o = (uint32_t*)g_qx;
        for (int i = blockIdx.x * blockDim.x + threadIdx.x; i < n4; i += HALF * blockDim.x) {
            float4 v = x4[i];
            int q0 = __float2int_rn(v.x * inv);
            int q1 = __float2int_rn(v.y * inv);
            int q2 = __float2int_rn(v.z * inv);
            int q3 = __float2int_rn(v.w * inv);
            o[i] = (q0 & 0xFF) | ((q1 & 0xFF) << 8) | ((q2 & 0xFF) << 16) | ((uint32_t)(q3 & 0xFF) << 24);
        }
    } else {
        const int4* w4 = (const int4*)w;
        uint32_t* o = (uint32_t*)g_wt;
        for (int i = (blockIdx.x - HALF) * blockDim.x + threadIdx.x; i < n4; i += HALF * blockDim.x) {
            int4 v = w4[i];
            o[i] = (v.x & 0xFF) | ((v.y & 0xFF) << 8) | ((v.z & 0xFF) << 16) | ((uint32_t)(v.w & 0xFF) << 24);
        }
    }
}

// ===================== stage 3: per-warp fused tensor+dp4a GEMM (72/56), phase-staggered =====================
// CTA 128x128, 8 warps (one per 16 M-rows), 2 CTAs/SM.
// Even warps: tensor phase then dp4a. Odd warps: dp4a then tensor.
// At any instant each SMSP has warps feeding BOTH the tensor and fma pipes.
__global__ void __launch_bounds__(256, 2) k_gemm(const float* __restrict__ wscale,
                                                 const float* __restrict__ bias,
                                                 float* __restrict__ out) {
    extern __shared__ __align__(16) char smem[];
    const uint32_t sbase = smem_u32(smem);

    const int tid  = threadIdx.x;
    const int lane = tid & 31;
    const int wid  = tid >> 5;
    const int Mbase = blockIdx.y * 128;
    const int Nbase = blockIdx.x * 128;

    // ---- staging (all 256 threads): A rows r0, r0+64; B rows 128+r0, 192+r0 ----
    const int r0 = tid >> 2;             // 0..63
    const int cb = (tid & 3) * 16;       // byte col in 64B chunk
    const int8_t* gA0 = g_qx + (size_t)(Mbase + r0)      * IN_F + cb;
    const int8_t* gA1 = g_qx + (size_t)(Mbase + r0 + 64) * IN_F + cb;
    const int8_t* gB0 = g_wt + (size_t)(Nbase + r0)      * IN_F + cb;
    const int8_t* gB1 = g_wt + (size_t)(Nbase + r0 + 64) * IN_F + cb;
    const uint32_t sA0 = sbase + (uint32_t)r0 * ROWB + cb;
    const uint32_t sA1 = sA0 + 64u * ROWB;
    const uint32_t sB0 = sA0 + 128u * ROWB;
    const uint32_t sB1 = sA0 + 192u * ROWB;

    // ---- mma mapping: warp wid owns rows [16*wid, 16*wid+16), cols [0,72) ----
    const int tile = lane >> 3;
    const int sub  = lane & 7;
    const uint32_t aoffw = sbase + (uint32_t)(wid * 16 + (tile & 1) * 8 + sub) * ROWB
                         + (uint32_t)(tile >> 1) * 16;
    uint32_t boff[5];
    #pragma unroll
    for (int p = 0; p < 5; ++p)       // 5 x4-LDSMs cover fragment cols [0,80); MMAs use first 9 blocks
        boff[p] = sbase + (uint32_t)(128 + p * 16 + (tile >> 1) * 8 + sub) * ROWB
                + (uint32_t)(tile & 1) * 16;

    // ---- dp4a mapping: warp wid rows [16*wid,16*wid+16), cols [72,128) ----
    const int trow = lane >> 3;          // 0..3 -> rows 16*wid + trow + 4i
    const int tcol = lane & 7;           // 0..7 -> cols 72 + tcol + 8j (j<7)
    const uint32_t dA = sbase + (uint32_t)(wid * 16 + trow) * ROWB;       // +i*4*ROWB
    const uint32_t dB = sbase + (uint32_t)(128 + DPC0 + tcol) * ROWB;     // +j*8*ROWB

    int acc[NB_MMA][4];                  // mma accumulators (16x72)
    #pragma unroll
    for (int nb = 0; nb < NB_MMA; ++nb)
        #pragma unroll
        for (int f = 0; f < 4; ++f) acc[nb][f] = 0;
    int dacc[4][DPJ];                    // dp4a accumulators (16x56 warp tile)
    #pragma unroll
    for (int i = 0; i < 4; ++i)
        #pragma unroll
        for (int j = 0; j < DPJ; ++j) dacc[i][j] = 0;

    // prologue: issue stages 0..2
    #pragma unroll
    for (int s = 0; s < STAGES - 1; ++s) {
        const uint32_t so = (uint32_t)s * SSTR;
        const int ko = s * KC;
        cp16(sA0 + so, gA0 + ko);
        cp16(sA1 + so, gA1 + ko);
        cp16(sB0 + so, gB0 + ko);
        cp16(sB1 + so, gB1 + ko);
        cp_commit();
    }

    const bool dpfirst = (wid & 1);

    for (int it = 0; it < KITERS; ++it) {
        cp_wait2();                 // stage it landed
        __syncthreads();            // all warps done with stage it-1

        if (it + STAGES - 1 < KITERS) {
            const uint32_t so = (uint32_t)((it + STAGES - 1) & (STAGES - 1)) * SSTR;
            const int ko = (it + STAGES - 1) * KC;
            cp16(sA0 + so, gA0 + ko);
            cp16(sA1 + so, gA1 + ko);
            cp16(sB0 + so, gB0 + ko);
            cp16(sB1 + so, gB1 + ko);
        }
        cp_commit();

        const uint32_t so = (uint32_t)(it & (STAGES - 1)) * SSTR;

        // ---------- dp4a phase (odd warps run this FIRST) ----------
        if (dpfirst) {
            #pragma unroll
            for (int qb = 0; qb < 8; ++qb) {
                int a0[4], a1[4], b0[DPJ], b1[DPJ];
                #pragma unroll
                for (int i = 0; i < 4; ++i)
                    lds64(a0[i], a1[i], dA + so + (uint32_t)i * (4u * ROWB) + (uint32_t)qb * 8u);
                #pragma unroll
                for (int j = 0; j < DPJ; ++j)
                    lds64(b0[j], b1[j], dB + so + (uint32_t)j * (8u * ROWB) + (uint32_t)qb * 8u);
                #pragma unroll
                for (int i = 0; i < 4; ++i)
                    #pragma unroll
                    for (int j = 0; j < DPJ; ++j) {
                        dacc[i][j] = __dp4a(a0[i], b0[j], dacc[i][j]);
                        dacc[i][j] = __dp4a(a1[i], b1[j], dacc[i][j]);
                    }
            }
        }

        // ---------- tensor phase ----------
        #pragma unroll
        for (int ks = 0; ks < 2; ++ks) {
            uint32_t af[4];
            ldsm_x4(af, aoffw + so + ks * 32);
            #pragma unroll
            for (int p = 0; p < 5; ++p) {
                uint32_t r[4];
                ldsm_x4(r, boff[p] + so + ks * 32);
                mma_s8(acc[p * 2], af, r);                 // n-block 2p (always < 9)
                if (p * 2 + 1 < NB_MMA)
                    mma_s8(acc[p * 2 + 1], af, r + 2);     // n-block 2p+1 (skip 10th)
            }
        }

        // ---------- dp4a phase (even warps run this AFTER tensor) ----------
        if (!dpfirst) {
            #pragma unroll
            for (int qb = 0; qb < 8; ++qb) {
                int a0[4], a1[4], b0[DPJ], b1[DPJ];
                #pragma unroll
                for (int i = 0; i < 4; ++i)
                    lds64(a0[i], a1[i], dA + so + (uint32_t)i * (4u * ROWB) + (uint32_t)qb * 8u);
                #pragma unroll
                for (int j = 0; j < DPJ; ++j)
                    lds64(b0[j], b1[j], dB + so + (uint32_t)j * (8u * ROWB) + (uint32_t)qb * 8u);
                #pragma unroll
                for (int i = 0; i < 4; ++i)
                    #pragma unroll
                    for (int j = 0; j < DPJ; ++j) {
                        dacc[i][j] = __dp4a(a0[i], b0[j], dacc[i][j]);
                        dacc[i][j] = __dp4a(a1[i], b1[j], dacc[i][j]);
                    }
            }
        }
    }

    // ---------- epilogue: exact int32 -> fp32 scale + bias ----------
    const float s = g_scale * wscale[0];
    {   // mma tile: cols [0,72)
        const int g   = lane >> 2;
        const int tg2 = (lane & 3) * 2;
        const int row = Mbase + wid * 16 + g;
        #pragma unroll
        for (int nb = 0; nb < NB_MMA; ++nb) {
            const int col = Nbase + nb * 8 + tg2;
            const float2 bb = *(const float2*)(bias + col);
            float2 v0, v1;
            v0.x = fmaf((float)acc[nb][0], s, bb.x);
            v0.y = fmaf((float)acc[nb][1], s, bb.y);
            v1.x = fmaf((float)acc[nb][2], s, bb.x);
            v1.y = fmaf((float)acc[nb][3], s, bb.y);
            *(float2*)(out + (size_t)row * OUT_F + col)       = v0;
            *(float2*)(out + (size_t)(row + 8) * OUT_F + col) = v1;
        }
    }
    {   // dp4a tile: cols [72,128)
        #pragma unroll
        for (int j = 0; j < DPJ; ++j) {
            const int col = Nbase + DPC0 + tcol + 8 * j;
            const float bj = bias[col];
            #pragma unroll
            for (int i = 0; i < 4; ++i) {
                const int row = Mbase + wid * 16 + trow + 4 * i;
                out[(size_t)row * OUT_F + col] = fmaf((float)dacc[i][j], s, bj);
            }
        }
    }
}

// ===================== launch =====================
extern "C" void kernel_launch(void* const* d_in, const int* in_sizes, int n_in,
                              void* d_out, int out_size) {
    const float* x    = (const float*)d_in[0];
    const int*   qw   = (const int*)d_in[1];
    const float* ws   = (const float*)d_in[2];
    const float* bias = (const float*)d_in[3];
    float* out = (float*)d_out;

    k_maxabs<<<2048, 256>>>(x);
    k_finalize<<<1, 1024>>>();
    k_prep<<<2048, 256>>>(x, qw);
    cudaFuncSetAttribute(k_gemm, cudaFuncAttributeMaxDynamicSharedMemorySize, SMEM_TOTAL);
    k_gemm<<<dim3(OUT_F / 128, T / 128), 256, SMEM_TOTAL>>>(ws, bias, out);
}

// round 14
// speedup vs baseline: 1.0384x; 1.0273x over previous
#include <cuda_runtime.h>
#include <cuda_bf16.h>
#include <cstdint>

// ===================== problem dims / tiles =====================
static constexpr int T     = 4096;   // tokens (M)
static constexpr int IN_F  = 4096;   // K
static constexpr int OUT_F = 4096;   // N
static constexpr int KC    = 64;     // K chunk bytes (int8)
static constexpr int KITERS = IN_F / KC;   // 64
static constexpr int ROWB  = 80;     // smem row stride (conflict-free ldmatrix + lds)
static constexpr int STAGES = 4;
static constexpr int SSTR  = 256 * ROWB;             // bytes per stage (A rows 0-127, B rows 128-255)
static constexpr int SMEM_TOTAL = STAGES * SSTR;     // 81920
// N-split: tensor cols [0,72), dp4a cols [72,128)   (R10-verified optimum)
static constexpr int NB_MMA = 9;     // 9 x 8 = 72 tensor cols
static constexpr int DPC0   = 72;    // dp4a col base
static constexpr int DPJ    = 7;     // dp4a col-blocks (7 x 8 = 56 cols)

// ===================== device scratch =====================
__device__ float g_partial[2048];
__device__ float g_scale;
__device__ float g_inv;
__device__ __align__(16) int8_t g_qx[(size_t)T * IN_F];     // 16MB quantized activations
__device__ __align__(16) int8_t g_wt[(size_t)OUT_F * IN_F]; // 16MB int8 weights

// ===================== helpers =====================
__device__ __forceinline__ uint32_t smem_u32(const void* p) {
    uint32_t a;
    asm("{ .reg .u64 t; cvta.to.shared.u64 t, %1; cvt.u32.u64 %0, t; }" : "=r"(a) : "l"(p));
    return a;
}
__device__ __forceinline__ void ldsm_x4(uint32_t* r, uint32_t addr) {
    asm volatile("ldmatrix.sync.aligned.m8n8.x4.shared.b16 {%0,%1,%2,%3}, [%4];"
                 : "=r"(r[0]), "=r"(r[1]), "=r"(r[2]), "=r"(r[3]) : "r"(addr));
}
__device__ __forceinline__ void mma_s8(int* c, const uint32_t* a, const uint32_t* b) {
    asm volatile(
        "mma.sync.aligned.m16n8k32.row.col.s32.s8.s8.s32 "
        "{%0,%1,%2,%3}, {%4,%5,%6,%7}, {%8,%9}, {%0,%1,%2,%3};"
        : "+r"(c[0]), "+r"(c[1]), "+r"(c[2]), "+r"(c[3])
        : "r"(a[0]), "r"(a[1]), "r"(a[2]), "r"(a[3]), "r"(b[0]), "r"(b[1]));
}
__device__ __forceinline__ void lds64(int& v0, int& v1, uint32_t addr) {
    asm volatile("ld.shared.v2.b32 {%0,%1}, [%2];" : "=r"(v0), "=r"(v1) : "r"(addr));
}
__device__ __forceinline__ void cp16(uint32_t saddr, const void* gaddr) {
    asm volatile("cp.async.cg.shared.global [%0], [%1], 16;" :: "r"(saddr), "l"(gaddr));
}
__device__ __forceinline__ void cp_commit() {
    asm volatile("cp.async.commit_group;" ::: "memory");
}
__device__ __forceinline__ void cp_wait2() {
    asm volatile("cp.async.wait_group 2;" ::: "memory");
}

// ===================== stage 1: max|x| =====================
__global__ void k_maxabs(const float* __restrict__ x) {
    __shared__ float red[256];
    float m = 0.f;
    const float4* x4 = (const float4*)x;
    const int n4 = T * IN_F / 4;
    for (int i = blockIdx.x * blockDim.x + threadIdx.x; i < n4; i += gridDim.x * blockDim.x) {
        float4 v = x4[i];
        m = fmaxf(m, fmaxf(fmaxf(fabsf(v.x), fabsf(v.y)), fmaxf(fabsf(v.z), fabsf(v.w))));
    }
    red[threadIdx.x] = m;
    __syncthreads();
    #pragma unroll
    for (int s = 128; s > 0; s >>= 1) {
        if (threadIdx.x < s) red[threadIdx.x] = fmaxf(red[threadIdx.x], red[threadIdx.x + s]);
        __syncthreads();
    }
    if (threadIdx.x == 0) g_partial[blockIdx.x] = red[0];
}

__global__ void k_finalize() {
    __shared__ float red[1024];
    red[threadIdx.x] = fmaxf(g_partial[threadIdx.x], g_partial[threadIdx.x + 1024]);
    __syncthreads();
    #pragma unroll
    for (int s = 512; s > 0; s >>= 1) {
        if (threadIdx.x < s) red[threadIdx.x] = fmaxf(red[threadIdx.x], red[threadIdx.x + s]);
        __syncthreads();
    }
    if (threadIdx.x == 0) {
        float sc = __fdiv_rn(red[0], 127.0f);
        g_scale = sc;
        g_inv = __fdiv_rn(1.0f, sc);
    }
}

// ===================== stage 2: fused quantize-x + weight-convert =====================
__global__ void k_prep(const float* __restrict__ x, const int* __restrict__ w) {
    const int HALF = 1024;
    const int n4 = T * IN_F / 4;
    if (blockIdx.x < HALF) {
        const float inv = g_inv;
        const float4* x4 = (const float4*)x;
        uint32_t* o = (uint32_t*)g_qx;
        for (int i = blockIdx.x * blockDim.x + threadIdx.x; i < n4; i += HALF * blockDim.x) {
            float4 v = x4[i];
            int q0 = __float2int_rn(v.x * inv);
            int q1 = __float2int_rn(v.y * inv);
            int q2 = __float2int_rn(v.z * inv);
            int q3 = __float2int_rn(v.w * inv);
            o[i] = (q0 & 0xFF) | ((q1 & 0xFF) << 8) | ((q2 & 0xFF) << 16) | ((uint32_t)(q3 & 0xFF) << 24);
        }
    } else {
        const int4* w4 = (const int4*)w;
        uint32_t* o = (uint32_t*)g_wt;
        for (int i = (blockIdx.x - HALF) * blockDim.x + threadIdx.x; i < n4; i += HALF * blockDim.x) {
            int4 v = w4[i];
            o[i] = (v.x & 0xFF) | ((v.y & 0xFF) << 8) | ((v.z & 0xFF) << 16) | ((uint32_t)(v.w & 0xFF) << 24);
        }
    }
}

// ===================== stage 3: per-warp fused tensor+dp4a GEMM (72/56), pipelined fragments =====================
// CTA 128x128, 8 warps (one per 16 M-rows), 2 CTAs/SM.
// Tensor phase software-pipelines B-fragment LDSMs one step ahead of the MMAs.
__global__ void __launch_bounds__(256, 2) k_gemm(const float* __restrict__ wscale,
                                                 const float* __restrict__ bias,
                                                 float* __restrict__ out) {
    extern __shared__ __align__(16) char smem[];
    const uint32_t sbase = smem_u32(smem);

    const int tid  = threadIdx.x;
    const int lane = tid & 31;
    const int wid  = tid >> 5;
    const int Mbase = blockIdx.y * 128;
    const int Nbase = blockIdx.x * 128;

    // ---- staging (all 256 threads): A rows r0, r0+64; B rows 128+r0, 192+r0 ----
    const int r0 = tid >> 2;             // 0..63
    const int cb = (tid & 3) * 16;       // byte col in 64B chunk
    const int8_t* gA0 = g_qx + (size_t)(Mbase + r0)      * IN_F + cb;
    const int8_t* gA1 = g_qx + (size_t)(Mbase + r0 + 64) * IN_F + cb;
    const int8_t* gB0 = g_wt + (size_t)(Nbase + r0)      * IN_F + cb;
    const int8_t* gB1 = g_wt + (size_t)(Nbase + r0 + 64) * IN_F + cb;
    const uint32_t sA0 = sbase + (uint32_t)r0 * ROWB + cb;
    const uint32_t sA1 = sA0 + 64u * ROWB;
    const uint32_t sB0 = sA0 + 128u * ROWB;
    const uint32_t sB1 = sA0 + 192u * ROWB;

    // ---- mma mapping: warp wid owns rows [16*wid, 16*wid+16), cols [0,72) ----
    const int tile = lane >> 3;
    const int sub  = lane & 7;
    const uint32_t aoffw = sbase + (uint32_t)(wid * 16 + (tile & 1) * 8 + sub) * ROWB
                         + (uint32_t)(tile >> 1) * 16;
    uint32_t boff[5];
    #pragma unroll
    for (int p = 0; p < 5; ++p)       // 5 x4-LDSMs cover fragment cols [0,80); MMAs use first 9 blocks
        boff[p] = sbase + (uint32_t)(128 + p * 16 + (tile >> 1) * 8 + sub) * ROWB
                + (uint32_t)(tile & 1) * 16;

    // ---- dp4a mapping: warp wid rows [16*wid,16*wid+16), cols [72,128) ----
    const int trow = lane >> 3;          // 0..3 -> rows 16*wid + trow + 4i
    const int tcol = lane & 7;           // 0..7 -> cols 72 + tcol + 8j (j<7)
    const uint32_t dA = sbase + (uint32_t)(wid * 16 + trow) * ROWB;       // +i*4*ROWB
    const uint32_t dB = sbase + (uint32_t)(128 + DPC0 + tcol) * ROWB;     // +j*8*ROWB

    int acc[NB_MMA][4];                  // mma accumulators (16x72)
    #pragma unroll
    for (int nb = 0; nb < NB_MMA; ++nb)
        #pragma unroll
        for (int f = 0; f < 4; ++f) acc[nb][f] = 0;
    int dacc[4][DPJ];                    // dp4a accumulators (16x56 warp tile)
    #pragma unroll
    for (int i = 0; i < 4; ++i)
        #pragma unroll
        for (int j = 0; j < DPJ; ++j) dacc[i][j] = 0;

    // prologue: issue stages 0..2
    #pragma unroll
    for (int s = 0; s < STAGES - 1; ++s) {
        const uint32_t so = (uint32_t)s * SSTR;
        const int ko = s * KC;
        cp16(sA0 + so, gA0 + ko);
        cp16(sA1 + so, gA1 + ko);
        cp16(sB0 + so, gB0 + ko);
        cp16(sB1 + so, gB1 + ko);
        cp_commit();
    }

    for (int it = 0; it < KITERS; ++it) {
        cp_wait2();                 // stage it landed
        __syncthreads();            // all warps done with stage it-1

        if (it + STAGES - 1 < KITERS) {
            const uint32_t so = (uint32_t)((it + STAGES - 1) & (STAGES - 1)) * SSTR;
            const int ko = (it + STAGES - 1) * KC;
            cp16(sA0 + so, gA0 + ko);
            cp16(sA1 + so, gA1 + ko);
            cp16(sB0 + so, gB0 + ko);
            cp16(sB1 + so, gB1 + ko);
        }
        cp_commit();

        const uint32_t so = (uint32_t)(it & (STAGES - 1)) * SSTR;

        // ---------- tensor path: B-fragments software-pipelined one LDSM ahead ----------
        #pragma unroll
        for (int ks = 0; ks < 2; ++ks) {
            uint32_t af[4];
            uint32_t rb[2][4];
            ldsm_x4(af, aoffw + so + ks * 32);
            ldsm_x4(rb[0], boff[0] + so + ks * 32);
            #pragma unroll
            for (int p = 0; p < 5; ++p) {
                if (p < 4)
                    ldsm_x4(rb[(p + 1) & 1], boff[p + 1] + so + ks * 32);  // prefetch next frag
                const uint32_t* r = rb[p & 1];
                mma_s8(acc[p * 2], af, r);                 // n-block 2p (always < 9)
                if (p * 2 + 1 < NB_MMA)
                    mma_s8(acc[p * 2 + 1], af, r + 2);     // n-block 2p+1 (skip 10th)
            }
        }

        // ---------- dp4a path: streams on fma/alu pipe while IMMAs drain ----------
        #pragma unroll
        for (int qb = 0; qb < 8; ++qb) {   // 8 q-pairs = 16 x 4-byte K-words
            int a0[4], a1[4], b0[DPJ], b1[DPJ];
            #pragma unroll
            for (int i = 0; i < 4; ++i)
                lds64(a0[i], a1[i], dA + so + (uint32_t)i * (4u * ROWB) + (uint32_t)qb * 8u);
            #pragma unroll
            for (int j = 0; j < DPJ; ++j)
                lds64(b0[j], b1[j], dB + so + (uint32_t)j * (8u * ROWB) + (uint32_t)qb * 8u);
            #pragma unroll
            for (int i = 0; i < 4; ++i)
                #pragma unroll
                for (int j = 0; j < DPJ; ++j) {
                    dacc[i][j] = __dp4a(a0[i], b0[j], dacc[i][j]);
                    dacc[i][j] = __dp4a(a1[i], b1[j], dacc[i][j]);
                }
        }
    }

    // ---------- epilogue: exact int32 -> fp32 scale + bias ----------
    const float s = g_scale * wscale[0];
    {   // mma tile: cols [0,72)
        const int g   = lane >> 2;
        const int tg2 = (lane & 3) * 2;
        const int row = Mbase + wid * 16 + g;
        #pragma unroll
        for (int nb = 0; nb < NB_MMA; ++nb) {
            const int col = Nbase + nb * 8 + tg2;
            const float2 bb = *(const float2*)(bias + col);
            float2 v0, v1;
            v0.x = fmaf((float)acc[nb][0], s, bb.x);
            v0.y = fmaf((float)acc[nb][1], s, bb.y);
            v1.x = fmaf((float)acc[nb][2], s, bb.x);
            v1.y = fmaf((float)acc[nb][3], s, bb.y);
            *(float2*)(out + (size_t)row * OUT_F + col)       = v0;
            *(float2*)(out + (size_t)(row + 8) * OUT_F + col) = v1;
        }
    }
    {   // dp4a tile: cols [72,128)
        #pragma unroll
        for (int j = 0; j < DPJ; ++j) {
            const int col = Nbase + DPC0 + tcol + 8 * j;
            const float bj = bias[col];
            #pragma unroll
            for (int i = 0; i < 4; ++i) {
                const int row = Mbase + wid * 16 + trow + 4 * i;
                out[(size_t)row * OUT_F + col] = fmaf((float)dacc[i][j], s, bj);
            }
        }
    }
}

// ===================== launch =====================
extern "C" void kernel_launch(void* const* d_in, const int* in_sizes, int n_in,
                              void* d_out, int out_size) {
    const float* x    = (const float*)d_in[0];
    const int*   qw   = (const int*)d_in[1];
    const float* ws   = (const float*)d_in[2];
    const float* bias = (const float*)d_in[3];
    float* out = (float*)d_out;

    k_maxabs<<<2048, 256>>>(x);
    k_finalize<<<1, 1024>>>();
    k_prep<<<2048, 256>>>(x, qw);
    cudaFuncSetAttribute(k_gemm, cudaFuncAttributeMaxDynamicSharedMemorySize, SMEM_TOTAL);
    k_gemm<<<dim3(OUT_F / 128, T / 128), 256, SMEM_TOTAL>>>(ws, bias, out);
}

// round 15
// speedup vs baseline: 1.1515x; 1.1089x over previous
#include <cuda_runtime.h>
#include <cuda_bf16.h>
#include <cstdint>

// ===================== problem dims / tiles =====================
static constexpr int T     = 4096;   // tokens (M)
static constexpr int IN_F  = 4096;   // K
static constexpr int OUT_F = 4096;   // N
static constexpr int KC    = 64;     // K chunk bytes (int8)
static constexpr int KITERS = IN_F / KC;   // 64
static constexpr int ROWB  = 80;     // smem row stride (conflict-free ldmatrix + lds)
static constexpr int STAGES = 4;
static constexpr int SSTR  = 256 * ROWB;             // bytes per stage (A rows 0-127, B rows 128-255)
static constexpr int SMEM_TOTAL = STAGES * SSTR;     // 81920
// N-split: tensor cols [0,72), dp4a cols [72,128)   (R10-verified optimum)
static constexpr int NB_MMA = 9;     // 9 x 8 = 72 tensor cols
static constexpr int DPC0   = 72;    // dp4a col base
static constexpr int DPJ    = 7;     // dp4a col-blocks (7 x 8 = 56 cols)

// ===================== device scratch =====================
__device__ float g_partial[2048];
__device__ float g_scale;
__device__ float g_inv;
__device__ __align__(16) int8_t g_qx[(size_t)T * IN_F];     // 16MB quantized activations
__device__ __align__(16) int8_t g_wt[(size_t)OUT_F * IN_F]; // 16MB int8 weights

// ===================== helpers =====================
__device__ __forceinline__ uint32_t smem_u32(const void* p) {
    uint32_t a;
    asm("{ .reg .u64 t; cvta.to.shared.u64 t, %1; cvt.u32.u64 %0, t; }" : "=r"(a) : "l"(p));
    return a;
}
__device__ __forceinline__ void ldsm_x4(uint32_t* r, uint32_t addr) {
    asm volatile("ldmatrix.sync.aligned.m8n8.x4.shared.b16 {%0,%1,%2,%3}, [%4];"
                 : "=r"(r[0]), "=r"(r[1]), "=r"(r[2]), "=r"(r[3]) : "r"(addr));
}
__device__ __forceinline__ void mma_s8(int* c, const uint32_t* a, const uint32_t* b) {
    asm volatile(
        "mma.sync.aligned.m16n8k32.row.col.s32.s8.s8.s32 "
        "{%0,%1,%2,%3}, {%4,%5,%6,%7}, {%8,%9}, {%0,%1,%2,%3};"
        : "+r"(c[0]), "+r"(c[1]), "+r"(c[2]), "+r"(c[3])
        : "r"(a[0]), "r"(a[1]), "r"(a[2]), "r"(a[3]), "r"(b[0]), "r"(b[1]));
}
__device__ __forceinline__ void lds64(int& v0, int& v1, uint32_t addr) {
    asm volatile("ld.shared.v2.b32 {%0,%1}, [%2];" : "=r"(v0), "=r"(v1) : "r"(addr));
}
__device__ __forceinline__ void cp16(uint32_t saddr, const void* gaddr) {
    asm volatile("cp.async.cg.shared.global [%0], [%1], 16;" :: "r"(saddr), "l"(gaddr));
}
__device__ __forceinline__ void cp_commit() {
    asm volatile("cp.async.commit_group;" ::: "memory");
}
__device__ __forceinline__ void cp_wait2() {
    asm volatile("cp.async.wait_group 2;" ::: "memory");
}

// ===================== stage 1: max|x| =====================
__global__ void k_maxabs(const float* __restrict__ x) {
    __shared__ float red[256];
    float m = 0.f;
    const float4* x4 = (const float4*)x;
    const int n4 = T * IN_F / 4;
    for (int i = blockIdx.x * blockDim.x + threadIdx.x; i < n4; i += gridDim.x * blockDim.x) {
        float4 v = x4[i];
        m = fmaxf(m, fmaxf(fmaxf(fabsf(v.x), fabsf(v.y)), fmaxf(fabsf(v.z), fabsf(v.w))));
    }
    red[threadIdx.x] = m;
    __syncthreads();
    #pragma unroll
    for (int s = 128; s > 0; s >>= 1) {
        if (threadIdx.x < s) red[threadIdx.x] = fmaxf(red[threadIdx.x], red[threadIdx.x + s]);
        __syncthreads();
    }
    if (threadIdx.x == 0) g_partial[blockIdx.x] = red[0];
}

__global__ void k_finalize() {
    __shared__ float red[1024];
    red[threadIdx.x] = fmaxf(g_partial[threadIdx.x], g_partial[threadIdx.x + 1024]);
    __syncthreads();
    #pragma unroll
    for (int s = 512; s > 0; s >>= 1) {
        if (threadIdx.x < s) red[threadIdx.x] = fmaxf(red[threadIdx.x], red[threadIdx.x + s]);
        __syncthreads();
    }
    if (threadIdx.x == 0) {
        float sc = __fdiv_rn(red[0], 127.0f);
        g_scale = sc;
        g_inv = __fdiv_rn(1.0f, sc);
    }
}

// ===================== stage 2: fused quantize-x + weight-convert =====================
__global__ void k_prep(const float* __restrict__ x, const int* __restrict__ w) {
    const int HALF = 1024;
    const int n4 = T * IN_F / 4;
    if (blockIdx.x < HALF) {
        const float inv = g_inv;
        const float4* x4 = (const float4*)x;
        uint32_t* o = (uint32_t*)g_qx;
        for (int i = blockIdx.x * blockDim.x + threadIdx.x; i < n4; i += HALF * blockDim.x) {
            float4 v = x4[i];
            int q0 = __float2int_rn(v.x * inv);
            int q1 = __float2int_rn(v.y * inv);
            int q2 = __float2int_rn(v.z * inv);
            int q3 = __float2int_rn(v.w * inv);
            o[i] = (q0 & 0xFF) | ((q1 & 0xFF) << 8) | ((q2 & 0xFF) << 16) | ((uint32_t)(q3 & 0xFF) << 24);
        }
    } else {
        const int4* w4 = (const int4*)w;
        uint32_t* o = (uint32_t*)g_wt;
        for (int i = (blockIdx.x - HALF) * blockDim.x + threadIdx.x; i < n4; i += HALF * blockDim.x) {
            int4 v = w4[i];
            o[i] = (v.x & 0xFF) | ((v.y & 0xFF) << 8) | ((v.z & 0xFF) << 16) | ((uint32_t)(v.w & 0xFF) << 24);
        }
    }
}

// ===================== stage 3: per-warp fused tensor+dp4a GEMM (72/56), SMSP-correct stagger =====================
// CTA 128x128, 8 warps, 2 CTAs/SM. SMSP s holds warps {s, s+4} per CTA:
// warps 0-3 run tensor->dp4a, warps 4-7 run dp4a->tensor, so EVERY SMSP feeds
// both the tensor and fma pipes at all times.
__global__ void __launch_bounds__(256, 2) k_gemm(const float* __restrict__ wscale,
                                                 const float* __restrict__ bias,
                                                 float* __restrict__ out) {
    extern __shared__ __align__(16) char smem[];
    const uint32_t sbase = smem_u32(smem);

    const int tid  = threadIdx.x;
    const int lane = tid & 31;
    const int wid  = tid >> 5;
    const int Mbase = blockIdx.y * 128;
    const int Nbase = blockIdx.x * 128;

    // ---- staging (all 256 threads): A rows r0, r0+64; B rows 128+r0, 192+r0 ----
    const int r0 = tid >> 2;             // 0..63
    const int cb = (tid & 3) * 16;       // byte col in 64B chunk
    const int8_t* gA0 = g_qx + (size_t)(Mbase + r0)      * IN_F + cb;
    const int8_t* gA1 = g_qx + (size_t)(Mbase + r0 + 64) * IN_F + cb;
    const int8_t* gB0 = g_wt + (size_t)(Nbase + r0)      * IN_F + cb;
    const int8_t* gB1 = g_wt + (size_t)(Nbase + r0 + 64) * IN_F + cb;
    const uint32_t sA0 = sbase + (uint32_t)r0 * ROWB + cb;
    const uint32_t sA1 = sA0 + 64u * ROWB;
    const uint32_t sB0 = sA0 + 128u * ROWB;
    const uint32_t sB1 = sA0 + 192u * ROWB;

    // ---- mma mapping: warp wid owns rows [16*wid, 16*wid+16), cols [0,72) ----
    const int tile = lane >> 3;
    const int sub  = lane & 7;
    const uint32_t aoffw = sbase + (uint32_t)(wid * 16 + (tile & 1) * 8 + sub) * ROWB
                         + (uint32_t)(tile >> 1) * 16;
    uint32_t boff[5];
    #pragma unroll
    for (int p = 0; p < 5; ++p)       // 5 x4-LDSMs cover fragment cols [0,80); MMAs use first 9 blocks
        boff[p] = sbase + (uint32_t)(128 + p * 16 + (tile >> 1) * 8 + sub) * ROWB
                + (uint32_t)(tile & 1) * 16;

    // ---- dp4a mapping: warp wid rows [16*wid,16*wid+16), cols [72,128) ----
    const int trow = lane >> 3;          // 0..3 -> rows 16*wid + trow + 4i
    const int tcol = lane & 7;           // 0..7 -> cols 72 + tcol + 8j (j<7)
    const uint32_t dA = sbase + (uint32_t)(wid * 16 + trow) * ROWB;       // +i*4*ROWB
    const uint32_t dB = sbase + (uint32_t)(128 + DPC0 + tcol) * ROWB;     // +j*8*ROWB

    int acc[NB_MMA][4];                  // mma accumulators (16x72)
    #pragma unroll
    for (int nb = 0; nb < NB_MMA; ++nb)
        #pragma unroll
        for (int f = 0; f < 4; ++f) acc[nb][f] = 0;
    int dacc[4][DPJ];                    // dp4a accumulators (16x56 warp tile)
    #pragma unroll
    for (int i = 0; i < 4; ++i)
        #pragma unroll
        for (int j = 0; j < DPJ; ++j) dacc[i][j] = 0;

    // prologue: issue stages 0..2
    #pragma unroll
    for (int s = 0; s < STAGES - 1; ++s) {
        const uint32_t so = (uint32_t)s * SSTR;
        const int ko = s * KC;
        cp16(sA0 + so, gA0 + ko);
        cp16(sA1 + so, gA1 + ko);
        cp16(sB0 + so, gB0 + ko);
        cp16(sB1 + so, gB1 + ko);
        cp_commit();
    }

    // SMSP-correct phase stagger: SMSP s = warps {s, s+4}; wid<4 tensor-first, wid>=4 dp4a-first
    const bool dpfirst = ((wid >> 2) & 1) != 0;

    for (int it = 0; it < KITERS; ++it) {
        cp_wait2();                 // stage it landed
        __syncthreads();            // all warps done with stage it-1

        if (it + STAGES - 1 < KITERS) {
            const uint32_t so = (uint32_t)((it + STAGES - 1) & (STAGES - 1)) * SSTR;
            const int ko = (it + STAGES - 1) * KC;
            cp16(sA0 + so, gA0 + ko);
            cp16(sA1 + so, gA1 + ko);
            cp16(sB0 + so, gB0 + ko);
            cp16(sB1 + so, gB1 + ko);
        }
        cp_commit();

        const uint32_t so = (uint32_t)(it & (STAGES - 1)) * SSTR;

        // ---------- dp4a phase (warps 4-7 run this FIRST) ----------
        if (dpfirst) {
            #pragma unroll
            for (int qb = 0; qb < 8; ++qb) {
                int a0[4], a1[4], b0[DPJ], b1[DPJ];
                #pragma unroll
                for (int i = 0; i < 4; ++i)
                    lds64(a0[i], a1[i], dA + so + (uint32_t)i * (4u * ROWB) + (uint32_t)qb * 8u);
                #pragma unroll
                for (int j = 0; j < DPJ; ++j)
                    lds64(b0[j], b1[j], dB + so + (uint32_t)j * (8u * ROWB) + (uint32_t)qb * 8u);
                #pragma unroll
                for (int i = 0; i < 4; ++i)
                    #pragma unroll
                    for (int j = 0; j < DPJ; ++j) {
                        dacc[i][j] = __dp4a(a0[i], b0[j], dacc[i][j]);
                        dacc[i][j] = __dp4a(a1[i], b1[j], dacc[i][j]);
                    }
            }
        }

        // ---------- tensor phase: B-fragments software-pipelined one LDSM ahead ----------
        #pragma unroll
        for (int ks = 0; ks < 2; ++ks) {
            uint32_t af[4];
            uint32_t rb[2][4];
            ldsm_x4(af, aoffw + so + ks * 32);
            ldsm_x4(rb[0], boff[0] + so + ks * 32);
            #pragma unroll
            for (int p = 0; p < 5; ++p) {
                if (p < 4)
                    ldsm_x4(rb[(p + 1) & 1], boff[p + 1] + so + ks * 32);  // prefetch next frag
                const uint32_t* r = rb[p & 1];
                mma_s8(acc[p * 2], af, r);                 // n-block 2p (always < 9)
                if (p * 2 + 1 < NB_MMA)
                    mma_s8(acc[p * 2 + 1], af, r + 2);     // n-block 2p+1 (skip 10th)
            }
        }

        // ---------- dp4a phase (warps 0-3 run this AFTER tensor) ----------
        if (!dpfirst) {
            #pragma unroll
            for (int qb = 0; qb < 8; ++qb) {
                int a0[4], a1[4], b0[DPJ], b1[DPJ];
                #pragma unroll
                for (int i = 0; i < 4; ++i)
                    lds64(a0[i], a1[i], dA + so + (uint32_t)i * (4u * ROWB) + (uint32_t)qb * 8u);
                #pragma unroll
                for (int j = 0; j < DPJ; ++j)
                    lds64(b0[j], b1[j], dB + so + (uint32_t)j * (8u * ROWB) + (uint32_t)qb * 8u);
                #pragma unroll
                for (int i = 0; i < 4; ++i)
                    #pragma unroll
                    for (int j = 0; j < DPJ; ++j) {
                        dacc[i][j] = __dp4a(a0[i], b0[j], dacc[i][j]);
                        dacc[i][j] = __dp4a(a1[i], b1[j], dacc[i][j]);
                    }
            }
        }
    }

    // ---------- epilogue: exact int32 -> fp32 scale + bias ----------
    const float s = g_scale * wscale[0];
    {   // mma tile: cols [0,72)
        const int g   = lane >> 2;
        const int tg2 = (lane & 3) * 2;
        const int row = Mbase + wid * 16 + g;
        #pragma unroll
        for (int nb = 0; nb < NB_MMA; ++nb) {
            const int col = Nbase + nb * 8 + tg2;
            const float2 bb = *(const float2*)(bias + col);
            float2 v0, v1;
            v0.x = fmaf((float)acc[nb][0], s, bb.x);
            v0.y = fmaf((float)acc[nb][1], s, bb.y);
            v1.x = fmaf((float)acc[nb][2], s, bb.x);
            v1.y = fmaf((float)acc[nb][3], s, bb.y);
            *(float2*)(out + (size_t)row * OUT_F + col)       = v0;
            *(float2*)(out + (size_t)(row + 8) * OUT_F + col) = v1;
        }
    }
    {   // dp4a tile: cols [72,128)
        #pragma unroll
        for (int j = 0; j < DPJ; ++j) {
            const int col = Nbase + DPC0 + tcol + 8 * j;
            const float bj = bias[col];
            #pragma unroll
            for (int i = 0; i < 4; ++i) {
                const int row = Mbase + wid * 16 + trow + 4 * i;
                out[(size_t)row * OUT_F + col] = fmaf((float)dacc[i][j], s, bj);
            }
        }
    }
}

// ===================== launch =====================
extern "C" void kernel_launch(void* const* d_in, const int* in_sizes, int n_in,
                              void* d_out, int out_size) {
    const float* x    = (const float*)d_in[0];
    const int*   qw   = (const int*)d_in[1];
    const float* ws   = (const float*)d_in[2];
    const float* bias = (const float*)d_in[3];
    float* out = (float*)d_out;

    k_maxabs<<<2048, 256>>>(x);
    k_finalize<<<1, 1024>>>();
    k_prep<<<2048, 256>>>(x, qw);
    cudaFuncSetAttribute(k_gemm, cudaFuncAttributeMaxDynamicSharedMemorySize, SMEM_TOTAL);
    k_gemm<<<dim3(OUT_F / 128, T / 128), 256, SMEM_TOTAL>>>(ws, bias, out);
}

// round 16
// speedup vs baseline: 1.1714x; 1.0173x over previous
#include <cuda_runtime.h>
#include <cuda_bf16.h>
#include <cstdint>

// ===================== problem dims / tiles =====================
static constexpr int T     = 4096;   // tokens (M)
static constexpr int IN_F  = 4096;   // K
static constexpr int OUT_F = 4096;   // N
static constexpr int KC    = 64;     // K chunk bytes (int8)
static constexpr int KITERS = IN_F / KC;   // 64
static constexpr int ROWB  = 80;     // smem row stride (conflict-free ldmatrix + lds)
static constexpr int STAGES = 4;
static constexpr int SSTR  = 256 * ROWB;             // bytes per stage (A rows 0-127, B rows 128-255)
static constexpr int SMEM_TOTAL = STAGES * SSTR;     // 81920
// N-split: tensor cols [0,64), dp4a cols [64,128)   (overlap-rebalanced)
static constexpr int NB_MMA = 8;     // 8 x 8 = 64 tensor cols
static constexpr int DPC0   = 64;    // dp4a col base
static constexpr int DPJ    = 8;     // dp4a col-blocks (8 x 8 = 64 cols)

// ===================== device scratch =====================
__device__ float g_partial[2048];
__device__ float g_scale;
__device__ float g_inv;
__device__ __align__(16) int8_t g_qx[(size_t)T * IN_F];     // 16MB quantized activations
__device__ __align__(16) int8_t g_wt[(size_t)OUT_F * IN_F]; // 16MB int8 weights

// ===================== helpers =====================
__device__ __forceinline__ uint32_t smem_u32(const void* p) {
    uint32_t a;
    asm("{ .reg .u64 t; cvta.to.shared.u64 t, %1; cvt.u32.u64 %0, t; }" : "=r"(a) : "l"(p));
    return a;
}
__device__ __forceinline__ void ldsm_x4(uint32_t* r, uint32_t addr) {
    asm volatile("ldmatrix.sync.aligned.m8n8.x4.shared.b16 {%0,%1,%2,%3}, [%4];"
                 : "=r"(r[0]), "=r"(r[1]), "=r"(r[2]), "=r"(r[3]) : "r"(addr));
}
__device__ __forceinline__ void mma_s8(int* c, const uint32_t* a, const uint32_t* b) {
    asm volatile(
        "mma.sync.aligned.m16n8k32.row.col.s32.s8.s8.s32 "
        "{%0,%1,%2,%3}, {%4,%5,%6,%7}, {%8,%9}, {%0,%1,%2,%3};"
        : "+r"(c[0]), "+r"(c[1]), "+r"(c[2]), "+r"(c[3])
        : "r"(a[0]), "r"(a[1]), "r"(a[2]), "r"(a[3]), "r"(b[0]), "r"(b[1]));
}
__device__ __forceinline__ void lds64(int& v0, int& v1, uint32_t addr) {
    asm volatile("ld.shared.v2.b32 {%0,%1}, [%2];" : "=r"(v0), "=r"(v1) : "r"(addr));
}
__device__ __forceinline__ void cp16(uint32_t saddr, const void* gaddr) {
    asm volatile("cp.async.cg.shared.global [%0], [%1], 16;" :: "r"(saddr), "l"(gaddr));
}
__device__ __forceinline__ void cp_commit() {
    asm volatile("cp.async.commit_group;" ::: "memory");
}
__device__ __forceinline__ void cp_wait2() {
    asm volatile("cp.async.wait_group 2;" ::: "memory");
}

// ===================== stage 1: max|x| =====================
__global__ void k_maxabs(const float* __restrict__ x) {
    __shared__ float red[256];
    float m = 0.f;
    const float4* x4 = (const float4*)x;
    const int n4 = T * IN_F / 4;
    for (int i = blockIdx.x * blockDim.x + threadIdx.x; i < n4; i += gridDim.x * blockDim.x) {
        float4 v = x4[i];
        m = fmaxf(m, fmaxf(fmaxf(fabsf(v.x), fabsf(v.y)), fmaxf(fabsf(v.z), fabsf(v.w))));
    }
    red[threadIdx.x] = m;
    __syncthreads();
    #pragma unroll
    for (int s = 128; s > 0; s >>= 1) {
        if (threadIdx.x < s) red[threadIdx.x] = fmaxf(red[threadIdx.x], red[threadIdx.x + s]);
        __syncthreads();
    }
    if (threadIdx.x == 0) g_partial[blockIdx.x] = red[0];
}

__global__ void k_finalize() {
    __shared__ float red[1024];
    red[threadIdx.x] = fmaxf(g_partial[threadIdx.x], g_partial[threadIdx.x + 1024]);
    __syncthreads();
    #pragma unroll
    for (int s = 512; s > 0; s >>= 1) {
        if (threadIdx.x < s) red[threadIdx.x] = fmaxf(red[threadIdx.x], red[threadIdx.x + s]);
        __syncthreads();
    }
    if (threadIdx.x == 0) {
        float sc = __fdiv_rn(red[0], 127.0f);
        g_scale = sc;
        g_inv = __fdiv_rn(1.0f, sc);
    }
}

// ===================== stage 2: fused quantize-x + weight-convert =====================
__global__ void k_prep(const float* __restrict__ x, const int* __restrict__ w) {
    const int HALF = 1024;
    const int n4 = T * IN_F / 4;
    if (blockIdx.x < HALF) {
        const float inv = g_inv;
        const float4* x4 = (const float4*)x;
        uint32_t* o = (uint32_t*)g_qx;
        for (int i = blockIdx.x * blockDim.x + threadIdx.x; i < n4; i += HALF * blockDim.x) {
            float4 v = x4[i];
            int q0 = __float2int_rn(v.x * inv);
            int q1 = __float2int_rn(v.y * inv);
            int q2 = __float2int_rn(v.z * inv);
            int q3 = __float2int_rn(v.w * inv);
            o[i] = (q0 & 0xFF) | ((q1 & 0xFF) << 8) | ((q2 & 0xFF) << 16) | ((uint32_t)(q3 & 0xFF) << 24);
        }
    } else {
        const int4* w4 = (const int4*)w;
        uint32_t* o = (uint32_t*)g_wt;
        for (int i = (blockIdx.x - HALF) * blockDim.x + threadIdx.x; i < n4; i += HALF * blockDim.x) {
            int4 v = w4[i];
            o[i] = (v.x & 0xFF) | ((v.y & 0xFF) << 8) | ((v.z & 0xFF) << 16) | ((uint32_t)(v.w & 0xFF) << 24);
        }
    }
}

// ===================== stage 3: per-warp fused tensor+dp4a GEMM (64/64), SMSP-staggered =====================
// CTA 128x128, 8 warps, 2 CTAs/SM. SMSP s holds warps {s, s+4} per CTA:
// warps 0-3 run tensor->dp4a, warps 4-7 run dp4a->tensor, so EVERY SMSP feeds
// both the tensor and fma pipes at all times.
__global__ void __launch_bounds__(256, 2) k_gemm(const float* __restrict__ wscale,
                                                 const float* __restrict__ bias,
                                                 float* __restrict__ out) {
    extern __shared__ __align__(16) char smem[];
    const uint32_t sbase = smem_u32(smem);

    const int tid  = threadIdx.x;
    const int lane = tid & 31;
    const int wid  = tid >> 5;
    const int Mbase = blockIdx.y * 128;
    const int Nbase = blockIdx.x * 128;

    // ---- staging (all 256 threads): A rows r0, r0+64; B rows 128+r0, 192+r0 ----
    const int r0 = tid >> 2;             // 0..63
    const int cb = (tid & 3) * 16;       // byte col in 64B chunk
    const int8_t* gA0 = g_qx + (size_t)(Mbase + r0)      * IN_F + cb;
    const int8_t* gA1 = g_qx + (size_t)(Mbase + r0 + 64) * IN_F + cb;
    const int8_t* gB0 = g_wt + (size_t)(Nbase + r0)      * IN_F + cb;
    const int8_t* gB1 = g_wt + (size_t)(Nbase + r0 + 64) * IN_F + cb;
    const uint32_t sA0 = sbase + (uint32_t)r0 * ROWB + cb;
    const uint32_t sA1 = sA0 + 64u * ROWB;
    const uint32_t sB0 = sA0 + 128u * ROWB;
    const uint32_t sB1 = sA0 + 192u * ROWB;

    // ---- mma mapping: warp wid owns rows [16*wid, 16*wid+16), cols [0,64) ----
    const int tile = lane >> 3;
    const int sub  = lane & 7;
    const uint32_t aoffw = sbase + (uint32_t)(wid * 16 + (tile & 1) * 8 + sub) * ROWB
                         + (uint32_t)(tile >> 1) * 16;
    uint32_t boff[4];
    #pragma unroll
    for (int p = 0; p < 4; ++p)       // 4 x4-LDSMs cover fragment cols [0,64) exactly
        boff[p] = sbase + (uint32_t)(128 + p * 16 + (tile >> 1) * 8 + sub) * ROWB
                + (uint32_t)(tile & 1) * 16;

    // ---- dp4a mapping: warp wid rows [16*wid,16*wid+16), cols [64,128) ----
    const int trow = lane >> 3;          // 0..3 -> rows 16*wid + trow + 4i
    const int tcol = lane & 7;           // 0..7 -> cols 64 + tcol + 8j (j<8)
    const uint32_t dA = sbase + (uint32_t)(wid * 16 + trow) * ROWB;       // +i*4*ROWB
    const uint32_t dB = sbase + (uint32_t)(128 + DPC0 + tcol) * ROWB;     // +j*8*ROWB

    int acc[NB_MMA][4];                  // mma accumulators (16x64)
    #pragma unroll
    for (int nb = 0; nb < NB_MMA; ++nb)
        #pragma unroll
        for (int f = 0; f < 4; ++f) acc[nb][f] = 0;
    int dacc[4][DPJ];                    // dp4a accumulators (16x64 warp tile)
    #pragma unroll
    for (int i = 0; i < 4; ++i)
        #pragma unroll
        for (int j = 0; j < DPJ; ++j) dacc[i][j] = 0;

    // prologue: issue stages 0..2
    #pragma unroll
    for (int s = 0; s < STAGES - 1; ++s) {
        const uint32_t so = (uint32_t)s * SSTR;
        const int ko = s * KC;
        cp16(sA0 + so, gA0 + ko);
        cp16(sA1 + so, gA1 + ko);
        cp16(sB0 + so, gB0 + ko);
        cp16(sB1 + so, gB1 + ko);
        cp_commit();
    }

    // SMSP-correct phase stagger: SMSP s = warps {s, s+4}; wid<4 tensor-first, wid>=4 dp4a-first
    const bool dpfirst = ((wid >> 2) & 1) != 0;

    for (int it = 0; it < KITERS; ++it) {
        cp_wait2();                 // stage it landed
        __syncthreads();            // all warps done with stage it-1

        if (it + STAGES - 1 < KITERS) {
            const uint32_t so = (uint32_t)((it + STAGES - 1) & (STAGES - 1)) * SSTR;
            const int ko = (it + STAGES - 1) * KC;
            cp16(sA0 + so, gA0 + ko);
            cp16(sA1 + so, gA1 + ko);
            cp16(sB0 + so, gB0 + ko);
            cp16(sB1 + so, gB1 + ko);
        }
        cp_commit();

        const uint32_t so = (uint32_t)(it & (STAGES - 1)) * SSTR;

        // ---------- dp4a phase (warps 4-7 run this FIRST) ----------
        if (dpfirst) {
            #pragma unroll
            for (int qb = 0; qb < 8; ++qb) {
                int a0[4], a1[4], b0[DPJ], b1[DPJ];
                #pragma unroll
                for (int i = 0; i < 4; ++i)
                    lds64(a0[i], a1[i], dA + so + (uint32_t)i * (4u * ROWB) + (uint32_t)qb * 8u);
                #pragma unroll
                for (int j = 0; j < DPJ; ++j)
                    lds64(b0[j], b1[j], dB + so + (uint32_t)j * (8u * ROWB) + (uint32_t)qb * 8u);
                #pragma unroll
                for (int i = 0; i < 4; ++i)
                    #pragma unroll
                    for (int j = 0; j < DPJ; ++j) {
                        dacc[i][j] = __dp4a(a0[i], b0[j], dacc[i][j]);
                        dacc[i][j] = __dp4a(a1[i], b1[j], dacc[i][j]);
                    }
            }
        }

        // ---------- tensor phase: B-fragments software-pipelined one LDSM ahead ----------
        #pragma unroll
        for (int ks = 0; ks < 2; ++ks) {
            uint32_t af[4];
            uint32_t rb[2][4];
            ldsm_x4(af, aoffw + so + ks * 32);
            ldsm_x4(rb[0], boff[0] + so + ks * 32);
            #pragma unroll
            for (int p = 0; p < 4; ++p) {
                if (p < 3)
                    ldsm_x4(rb[(p + 1) & 1], boff[p + 1] + so + ks * 32);  // prefetch next frag
                const uint32_t* r = rb[p & 1];
                mma_s8(acc[p * 2],     af, r);       // n-block 2p
                mma_s8(acc[p * 2 + 1], af, r + 2);   // n-block 2p+1
            }
        }

        // ---------- dp4a phase (warps 0-3 run this AFTER tensor) ----------
        if (!dpfirst) {
            #pragma unroll
            for (int qb = 0; qb < 8; ++qb) {
                int a0[4], a1[4], b0[DPJ], b1[DPJ];
                #pragma unroll
                for (int i = 0; i < 4; ++i)
                    lds64(a0[i], a1[i], dA + so + (uint32_t)i * (4u * ROWB) + (uint32_t)qb * 8u);
                #pragma unroll
                for (int j = 0; j < DPJ; ++j)
                    lds64(b0[j], b1[j], dB + so + (uint32_t)j * (8u * ROWB) + (uint32_t)qb * 8u);
                #pragma unroll
                for (int i = 0; i < 4; ++i)
                    #pragma unroll
                    for (int j = 0; j < DPJ; ++j) {
                        dacc[i][j] = __dp4a(a0[i], b0[j], dacc[i][j]);
                        dacc[i][j] = __dp4a(a1[i], b1[j], dacc[i][j]);
                    }
            }
        }
    }

    // ---------- epilogue: exact int32 -> fp32 scale + bias ----------
    const float s = g_scale * wscale[0];
    {   // mma tile: cols [0,64)
        const int g   = lane >> 2;
        const int tg2 = (lane & 3) * 2;
        const int row = Mbase + wid * 16 + g;
        #pragma unroll
        for (int nb = 0; nb < NB_MMA; ++nb) {
            const int col = Nbase + nb * 8 + tg2;
            const float2 bb = *(const float2*)(bias + col);
            float2 v0, v1;
            v0.x = fmaf((float)acc[nb][0], s, bb.x);
            v0.y = fmaf((float)acc[nb][1], s, bb.y);
            v1.x = fmaf((float)acc[nb][2], s, bb.x);
            v1.y = fmaf((float)acc[nb][3], s, bb.y);
            *(float2*)(out + (size_t)row * OUT_F + col)       = v0;
            *(float2*)(out + (size_t)(row + 8) * OUT_F + col) = v1;
        }
    }
    {   // dp4a tile: cols [64,128)
        #pragma unroll
        for (int j = 0; j < DPJ; ++j) {
            const int col = Nbase + DPC0 + tcol + 8 * j;
            const float bj = bias[col];
            #pragma unroll
            for (int i = 0; i < 4; ++i) {
                const int row = Mbase + wid * 16 + trow + 4 * i;
                out[(size_t)row * OUT_F + col] = fmaf((float)dacc[i][j], s, bj);
            }
        }
    }
}

// ===================== launch =====================
extern "C" void kernel_launch(void* const* d_in, const int* in_sizes, int n_in,
                              void* d_out, int out_size) {
    const float* x    = (const float*)d_in[0];
    const int*   qw   = (const int*)d_in[1];
    const float* ws   = (const float*)d_in[2];
    const float* bias = (const float*)d_in[3];
    float* out = (float*)d_out;

    k_maxabs<<<2048, 256>>>(x);
    k_finalize<<<1, 1024>>>();
    k_prep<<<2048, 256>>>(x, qw);
    cudaFuncSetAttribute(k_gemm, cudaFuncAttributeMaxDynamicSharedMemorySize, SMEM_TOTAL);
    k_gemm<<<dim3(OUT_F / 128, T / 128), 256, SMEM_TOTAL>>>(ws, bias, out);
}